// round 15
// baseline (speedup 1.0000x reference)
#include <cuda_runtime.h>
#include <cuda_fp16.h>
#include <mma.h>

using namespace nvcuda;

#define IN   128
#define HID  128
#define OUTF 64
#define NMAX 50000
#define CAP  128   // bucket capacity per node (Poisson(32) -> P(>=128) ~ 0)

// Scratch (device globals; no allocation allowed)
// INVARIANT: g_cnt is all-zero at kernel_launch entry (zeroed in k_decode epilogue;
// device globals start zero-initialized on first load).
__device__ __align__(128) unsigned int g_y1h[NMAX * HID / 2];   // x@W1; pre-scaled by dinv in k_prep
__device__ __align__(128) unsigned int g_hh [NMAX * HID / 2];   // relu hidden, half2 packed
__device__ __align__(128) unsigned int g_y2h[NMAX * OUTF / 2];  // (h@W2)*dinv[row], half2 packed
__device__ __align__(128) float g_z [NMAX * OUTF];              // final embeddings
__device__ __align__(16) __half g_W1h[IN * HID];
__device__ __align__(16) __half g_W2h[HID * OUTF];
__device__ float g_dinv[NMAX];
__device__ int   g_cnt[NMAX];
__device__ __align__(128) unsigned short g_bucket[NMAX * CAP];  // 16-bit src ids (N < 65536)

// ---------------- weight conversion (fp32 -> fp16) ----------------
__global__ void k_convW(const float* __restrict__ W1, const float* __restrict__ W2) {
    int i = blockIdx.x * blockDim.x + threadIdx.x;
    if (i < IN * HID) g_W1h[i] = __float2half(W1[i]);
    else if (i < IN * HID + HID * OUTF) g_W2h[i - IN * HID] = __float2half(W2[i - IN * HID]);
}

// ---------------- direct bucket fill (cnt pre-zeroed by previous call), 8 chains/thread ----
__global__ void __launch_bounds__(256) k_fill_direct(const int* __restrict__ ei, int E) {
    int stride = gridDim.x * blockDim.x;
    int e = blockIdx.x * blockDim.x + threadIdx.x;
#pragma unroll 8
    for (int k = 0; k < 8; k++) {
        int idx = e + k * stride;
        if (idx < E) {
            int s = ei[idx];
            int d = ei[E + idx];
            int pos = atomicAdd(&g_cnt[d], 1);
            if (pos < CAP) g_bucket[(size_t)d * CAP + pos] = (unsigned short)s;
        }
    }
}

// ---------------- prep (PDL, waits fill; gemm1 done via event before launch) ----------
// computes dinv AND pre-scales y1h in place: y1h[row] *= dinv[row]
__global__ void __launch_bounds__(256) k_prep(int n) {
    int gtid = (int)(blockIdx.x * 256u + threadIdx.x);  // uint2 index over n*32
    cudaGridDependencySynchronize();                    // wait for fill's cnt
    if (gtid >= n * 32) return;
    int row = gtid >> 5;
    float d = rsqrtf((float)(g_cnt[row] + 1));          // +1 self loop
    if ((gtid & 31) == 0) g_dinv[row] = d;
    uint2 p = ((uint2*)g_y1h)[gtid];
    float2 u = __half22float2(*(half2*)&p.x);
    float2 v = __half22float2(*(half2*)&p.y);
    half2 q0 = __float22half2_rn(make_float2(u.x * d, u.y * d));
    half2 q1 = __float22half2_rn(make_float2(v.x * d, v.y * d));
    p.x = *(unsigned int*)&q0; p.y = *(unsigned int*)&q1;
    ((uint2*)g_y1h)[gtid] = p;
}

// ---------------- GEMM1 (wmma): y1 = x @ W1, fp16 out, padded smem ----------------
#define G1_STRIDE 136
#define GEMM1_SMEM ((64 * G1_STRIDE + 128 * G1_STRIDE) * 2)
__global__ void __launch_bounds__(256) k_gemm1(const float* __restrict__ x, int n) {
    extern __shared__ __align__(16) unsigned char smd1[];
    __half* xs = (__half*)smd1;                          // [64][136]
    __half* ws = (__half*)(smd1 + 64 * G1_STRIDE * 2);   // [128][136]
    int row0 = blockIdx.x * 64;
    int tid = threadIdx.x;

    for (int i = tid; i < 64 * 32; i += 256) {
        int r = i >> 5, c4 = i & 31;
        float4 v = make_float4(0.f, 0.f, 0.f, 0.f);
        if (row0 + r < n) v = ((const float4*)x)[(size_t)(row0 + r) * 32 + c4];
        half2 h0 = __float22half2_rn(make_float2(v.x, v.y));
        half2 h1 = __float22half2_rn(make_float2(v.z, v.w));
        uint2 p; p.x = *(unsigned int*)&h0; p.y = *(unsigned int*)&h1;
        *(uint2*)(xs + r * G1_STRIDE + c4 * 4) = p;
    }
    for (int i = tid; i < 2048; i += 256) {
        int r = i >> 4, c8 = i & 15;
        uint4 p = ((const uint4*)g_W1h)[i];
        *(uint4*)(ws + r * G1_STRIDE + c8 * 8) = p;
    }
    __syncthreads();

    int warp = tid >> 5;
    int rowg = warp >> 1;
    int colh = warp & 1;

    wmma::fragment<wmma::accumulator, 16, 16, 16, float> c[4];
#pragma unroll
    for (int t = 0; t < 4; t++) wmma::fill_fragment(c[t], 0.f);

#pragma unroll
    for (int k = 0; k < 8; k++) {
        wmma::fragment<wmma::matrix_a, 16, 16, 16, __half, wmma::row_major> a;
        wmma::load_matrix_sync(a, xs + (rowg * 16) * G1_STRIDE + k * 16, G1_STRIDE);
#pragma unroll
        for (int t = 0; t < 4; t++) {
            wmma::fragment<wmma::matrix_b, 16, 16, 16, __half, wmma::row_major> b;
            wmma::load_matrix_sync(b, ws + (k * 16) * G1_STRIDE + colh * 64 + t * 16, G1_STRIDE);
            wmma::mma_sync(c[t], a, b, c[t]);
        }
    }
    __syncthreads();
    float* fbuf = (float*)smd1;  // [64][128] floats = 32KB
#pragma unroll
    for (int t = 0; t < 4; t++)
        wmma::store_matrix_sync(fbuf + (rowg * 16) * 128 + colh * 64 + t * 16, c[t], 128, wmma::mem_row_major);
    __syncthreads();

    for (int i = tid; i < 64 * 32; i += 256) {
        int r = i >> 5, c4 = i & 31;
        int row = row0 + r;
        if (row < n) {
            float4 v = ((float4*)fbuf)[i];
            half2 h0 = __float22half2_rn(make_float2(v.x, v.y));
            half2 h1 = __float22half2_rn(make_float2(v.z, v.w));
            uint2 p; p.x = *(unsigned int*)&h0; p.y = *(unsigned int*)&h1;
            ((uint2*)g_y1h)[(size_t)row * 32 + c4] = p;
        }
    }
}

// ---------------- agg1 (PDL): h = relu((sum y1s[s]) * dinv[i] + b1), fp16 out ----
// y1h pre-scaled by dinv[src] in k_prep: pure fp16 row sum.
__global__ void __launch_bounds__(256) k_agg1(const float* __restrict__ b1, int n) {
    int node = (int)((blockIdx.x * 256u + threadIdx.x) >> 5);
    int lane = threadIdx.x & 31;

    cudaGridDependencySynchronize();  // wait for k_prep (=> fill, dinv, scaled y1)
    if (node >= n) return;

    int deg = g_cnt[node];
    if (deg > CAP) deg = CAP;
    const unsigned short* bkt = g_bucket + (size_t)node * CAP;
    float dself = g_dinv[node];

    const uint2* y = (const uint2*)g_y1h;
    uint2 ps = y[(size_t)node * 32 + lane];  // self (pre-scaled)
    float2 a0 = __half22float2(*(half2*)&ps.x);
    float2 a1 = __half22float2(*(half2*)&ps.y);
    float4 acc = make_float4(a0.x, a0.y, a1.x, a1.y);

    int j = 0;
    for (; j + 3 < deg; j += 4) {
        int s0 = __ldg(&bkt[j]);
        int s1 = __ldg(&bkt[j + 1]);
        int s2 = __ldg(&bkt[j + 2]);
        int s3 = __ldg(&bkt[j + 3]);
        uint2 p0 = y[(size_t)s0 * 32 + lane];
        uint2 p1 = y[(size_t)s1 * 32 + lane];
        uint2 p2 = y[(size_t)s2 * 32 + lane];
        uint2 p3 = y[(size_t)s3 * 32 + lane];
        float2 u, v;
        u = __half22float2(*(half2*)&p0.x); v = __half22float2(*(half2*)&p0.y);
        acc.x += u.x; acc.y += u.y; acc.z += v.x; acc.w += v.y;
        u = __half22float2(*(half2*)&p1.x); v = __half22float2(*(half2*)&p1.y);
        acc.x += u.x; acc.y += u.y; acc.z += v.x; acc.w += v.y;
        u = __half22float2(*(half2*)&p2.x); v = __half22float2(*(half2*)&p2.y);
        acc.x += u.x; acc.y += u.y; acc.z += v.x; acc.w += v.y;
        u = __half22float2(*(half2*)&p3.x); v = __half22float2(*(half2*)&p3.y);
        acc.x += u.x; acc.y += u.y; acc.z += v.x; acc.w += v.y;
    }
    for (; j < deg; j++) {
        int s0 = __ldg(&bkt[j]);
        uint2 p0 = y[(size_t)s0 * 32 + lane];
        float2 u = __half22float2(*(half2*)&p0.x);
        float2 v = __half22float2(*(half2*)&p0.y);
        acc.x += u.x; acc.y += u.y; acc.z += v.x; acc.w += v.y;
    }

    float4 bb = ((const float4*)b1)[lane];
    float2 h0, h1;
    h0.x = fmaxf(acc.x * dself + bb.x, 0.f);
    h0.y = fmaxf(acc.y * dself + bb.y, 0.f);
    h1.x = fmaxf(acc.z * dself + bb.z, 0.f);
    h1.y = fmaxf(acc.w * dself + bb.w, 0.f);
    half2 q0 = __float22half2_rn(h0);
    half2 q1 = __float22half2_rn(h1);
    uint2 p; p.x = *(unsigned int*)&q0; p.y = *(unsigned int*)&q1;
    ((uint2*)g_hh)[(size_t)node * 32 + lane] = p;
}

// ---------------- GEMM2 (wmma): y2 = (h @ W2) * dinv[row], PDL ----------------
#define HS_STRIDE 136
#define WS_STRIDE 72
__global__ void __launch_bounds__(256) k_gemm2(int n) {
    extern __shared__ __align__(16) unsigned char smd[];
    __half* hs  = (__half*)smd;                       // [128][136]
    __half* w2s = (__half*)(smd + 128 * HS_STRIDE * 2);  // [128][72]
    int row0 = blockIdx.x * 128;
    int tid = threadIdx.x;

    // PRELUDE (independent of agg1): stage W2 tile
    for (int i = tid; i < 1024; i += 256) {
        int r = i >> 3, c8 = i & 7;
        uint4 p = ((const uint4*)g_W2h)[i];
        *(uint4*)(w2s + r * WS_STRIDE + c8 * 8) = p;
    }

    cudaGridDependencySynchronize();  // wait for agg1's h

    for (int i = tid; i < 128 * 32; i += 256) {
        int r = i >> 5, c4 = i & 31;
        uint2 p = make_uint2(0u, 0u);
        if (row0 + r < n) p = ((const uint2*)g_hh)[(size_t)(row0 + r) * 32 + c4];
        *(uint2*)(hs + r * HS_STRIDE + c4 * 4) = p;
    }
    __syncthreads();

    int warp = tid >> 5;  // each warp owns 16 rows x all 64 cols

    wmma::fragment<wmma::accumulator, 16, 16, 16, float> c[4];
#pragma unroll
    for (int t = 0; t < 4; t++) wmma::fill_fragment(c[t], 0.f);

#pragma unroll
    for (int k = 0; k < 8; k++) {
        wmma::fragment<wmma::matrix_a, 16, 16, 16, __half, wmma::row_major> a;
        wmma::load_matrix_sync(a, hs + (warp * 16) * HS_STRIDE + k * 16, HS_STRIDE);
#pragma unroll
        for (int t = 0; t < 4; t++) {
            wmma::fragment<wmma::matrix_b, 16, 16, 16, __half, wmma::row_major> b;
            wmma::load_matrix_sync(b, w2s + (k * 16) * WS_STRIDE + t * 16, WS_STRIDE);
            wmma::mma_sync(c[t], a, b, c[t]);
        }
    }
    __syncthreads();
    float* fbuf = (float*)smd;  // [128][64] floats = 32KB
#pragma unroll
    for (int t = 0; t < 4; t++)
        wmma::store_matrix_sync(fbuf + (warp * 16) * 64 + t * 16, c[t], 64, wmma::mem_row_major);
    __syncthreads();

    for (int i = tid; i < 128 * 16; i += 256) {
        int r = i >> 4, c4 = i & 15;
        int row = row0 + r;
        if (row < n) {
            float d = g_dinv[row];
            float4 v = ((float4*)fbuf)[i];
            half2 h0 = __float22half2_rn(make_float2(v.x * d, v.y * d));
            half2 h1 = __float22half2_rn(make_float2(v.z * d, v.w * d));
            uint2 p; p.x = *(unsigned int*)&h0; p.y = *(unsigned int*)&h1;
            ((uint2*)g_y2h)[(size_t)row * 16 + c4] = p;
        }
    }
}
#define GEMM2_SMEM (128 * HS_STRIDE * 2 + 128 * WS_STRIDE * 2)

// ---------------- agg2: z = (y2[i] + sum y2[src]) * dinv[i] + b2, PDL ----------------
__global__ void __launch_bounds__(256) k_agg2(const float* __restrict__ b2, int n) {
    int node = (int)((blockIdx.x * 256u + threadIdx.x) >> 5);
    int lane = threadIdx.x & 31;
    if (node >= n) { cudaGridDependencySynchronize(); return; }

    // PRELUDE (independent of gemm2): bucket metadata + bias + dinv
    int deg = g_cnt[node];
    if (deg > CAP) deg = CAP;
    const unsigned short* bkt = g_bucket + (size_t)node * CAP;
    float d = g_dinv[node];
    float2 bb = ((const float2*)b2)[lane];

    cudaGridDependencySynchronize();  // wait for gemm2's y2

    const unsigned int* y = g_y2h;
    unsigned int ps = y[(size_t)node * 32 + lane];  // self (already * dinv[self])
    float2 acc = __half22float2(*(half2*)&ps);

    int j = 0;
    for (; j + 3 < deg; j += 4) {
        int s0 = __ldg(&bkt[j]);
        int s1 = __ldg(&bkt[j + 1]);
        int s2 = __ldg(&bkt[j + 2]);
        int s3 = __ldg(&bkt[j + 3]);
        unsigned int p0 = y[(size_t)s0 * 32 + lane];
        unsigned int p1 = y[(size_t)s1 * 32 + lane];
        unsigned int p2 = y[(size_t)s2 * 32 + lane];
        unsigned int p3 = y[(size_t)s3 * 32 + lane];
        float2 u;
        u = __half22float2(*(half2*)&p0); acc.x += u.x; acc.y += u.y;
        u = __half22float2(*(half2*)&p1); acc.x += u.x; acc.y += u.y;
        u = __half22float2(*(half2*)&p2); acc.x += u.x; acc.y += u.y;
        u = __half22float2(*(half2*)&p3); acc.x += u.x; acc.y += u.y;
    }
    for (; j < deg; j++) {
        int s0 = __ldg(&bkt[j]);
        unsigned int p0 = y[(size_t)s0 * 32 + lane];
        float2 u = __half22float2(*(half2*)&p0);
        acc.x += u.x; acc.y += u.y;
    }

    float2 z = make_float2(acc.x * d + bb.x, acc.y * d + bb.y);
    ((float2*)g_z)[(size_t)node * 32 + lane] = z;
}

// ---------------- decode, PDL; epilogue re-zeroes g_cnt for the next call ----------------
__global__ void __launch_bounds__(256) k_decode(const int* __restrict__ eli, int EL,
                                                float* __restrict__ out, int n) {
    int gtid = (int)(blockIdx.x * 256u + threadIdx.x);
    int w = gtid >> 5;
    int lane = threadIdx.x & 31;

    // PRELUDE: edge endpoints (harness input, independent of agg2)
    int a = 0, b = 0;
    if (w < EL) { a = eli[w]; b = eli[EL + w]; }

    cudaGridDependencySynchronize();  // wait for agg2's z (agg2 = last reader of g_cnt)

    // restore the cnt==0 invariant for the next kernel_launch call / graph replay
    if (gtid < n) g_cnt[gtid] = 0;

    if (w >= EL) return;
    float2 za = ((const float2*)g_z)[(size_t)a * 32 + lane];
    float2 zb = ((const float2*)g_z)[(size_t)b * 32 + lane];
    float s = za.x * zb.x + za.y * zb.y;
#pragma unroll
    for (int o = 16; o; o >>= 1) s += __shfl_xor_sync(0xffffffffu, s, o);
    if (lane == 0) out[w] = s;
}

// ---------------- side stream + launch helpers ----------------
static cudaStream_t g_s1;
static cudaEvent_t g_ev0, g_evG;
namespace {
struct GInit {
    GInit() {
        cudaStreamCreateWithFlags(&g_s1, cudaStreamNonBlocking);
        cudaEventCreateWithFlags(&g_ev0, cudaEventDisableTiming);
        cudaEventCreateWithFlags(&g_evG, cudaEventDisableTiming);
        cudaFuncSetAttribute(k_gemm1, cudaFuncAttributeMaxDynamicSharedMemorySize, GEMM1_SMEM);
        cudaFuncSetAttribute(k_gemm2, cudaFuncAttributeMaxDynamicSharedMemorySize, GEMM2_SMEM);
    }
};
GInit g_init;
}

// helper: launch with PDL (programmatic stream serialization)
template <typename F, typename... Args>
static inline void launch_pdl(F func, dim3 grid, dim3 block, size_t smem,
                              cudaStream_t s, Args... args) {
    cudaLaunchConfig_t cfg = {};
    cfg.gridDim = grid;
    cfg.blockDim = block;
    cfg.dynamicSmemBytes = smem;
    cfg.stream = s;
    cudaLaunchAttribute attr[1];
    attr[0].id = cudaLaunchAttributeProgrammaticStreamSerialization;
    attr[0].val.programmaticStreamSerializationAllowed = 1;
    cfg.attrs = attr;
    cfg.numAttrs = 1;
    cudaLaunchKernelEx(&cfg, func, args...);
}

extern "C" void kernel_launch(void* const* d_in, const int* in_sizes, int n_in,
                              void* d_out, int out_size) {
    const float* x   = (const float*)d_in[0];
    const int*   ei  = (const int*)d_in[1];
    const int*   eli = (const int*)d_in[2];
    const float* W1  = (const float*)d_in[3];
    const float* b1  = (const float*)d_in[4];
    const float* W2  = (const float*)d_in[5];
    const float* b2  = (const float*)d_in[6];
    float* out = (float*)d_out;

    int N  = in_sizes[0] / IN;
    int E  = in_sizes[1] / 2;
    int EL = in_sizes[2] / 2;
    int eighth = (E + 7) / 8;

    // fork: branch B (weights conv + gemm1) on side stream
    cudaEventRecord(g_ev0, 0);
    cudaStreamWaitEvent(g_s1, g_ev0, 0);
    k_convW<<<(IN * HID + HID * OUTF + 255) / 256, 256, 0, g_s1>>>(W1, W2);
    k_gemm1<<<(N + 63) / 64, 256, GEMM1_SMEM, g_s1>>>(x, N);
    cudaEventRecord(g_evG, g_s1);

    // branch A: direct bucket CSR on main stream (cnt already zeroed by prior call)
    k_fill_direct<<<(eighth + 255) / 256, 256>>>(ei, E);

    // join gemm1 (y1 needed by k_prep), then PDL chain:
    // prep (dinv + prescale y1) -> agg1 -> gemm2 -> agg2 -> decode
    cudaStreamWaitEvent(0, g_evG, 0);
    launch_pdl(k_prep, dim3((N * 32 + 255) / 256), dim3(256), 0, (cudaStream_t)0, N);
    launch_pdl(k_agg1, dim3((N * 32 + 255) / 256), dim3(256), 0, (cudaStream_t)0, b1, N);
    launch_pdl(k_gemm2, dim3((N + 127) / 128), dim3(256), (size_t)GEMM2_SMEM, (cudaStream_t)0, N);
    launch_pdl(k_agg2, dim3((N * 32 + 255) / 256), dim3(256), 0, (cudaStream_t)0, b2, N);
    launch_pdl(k_decode, dim3((EL * 32 + 255) / 256), dim3(256), 0, (cudaStream_t)0, eli, EL, out, N);
}